// round 14
// baseline (speedup 1.0000x reference)
#include <cuda_runtime.h>
#include <cuda_fp16.h>
#include <cstdint>
#include <cstddef>

#define NE 8
#define NC 4096
#define ND 1024
#define NF 4096

// Device scratch (no allocs allowed)
__device__ __half g_Xh [(size_t)NE * NC * ND];   // X fp16
__device__ __half g_W1h[(size_t)NE * ND * NF];   // W1 fp16 (natural [D,F])
__device__ __half g_W2h[(size_t)NE * NF * ND];   // W2 fp16 (natural [F,D])
__device__ __half g_Hh [(size_t)NE * NC * NF];   // relu(X@W1) fp16

// ---------------- helpers ----------------
__device__ __forceinline__ uint32_t smem_u32(const void* p) {
    uint32_t a;
    asm("{ .reg .u64 t; cvta.to.shared.u64 t, %1; cvt.u32.u64 %0, t; }" : "=r"(a) : "l"(p));
    return a;
}
__device__ __forceinline__ void cp_async16(uint32_t dst, const void* src) {
    asm volatile("cp.async.cg.shared.global [%0], [%1], 16;" :: "r"(dst), "l"(src));
}
#define CP_COMMIT() asm volatile("cp.async.commit_group;" ::: "memory")
#define CP_WAIT1()  asm volatile("cp.async.wait_group 1;" ::: "memory")

__device__ __forceinline__ void ldmx4(uint32_t r[4], uint32_t addr) {
    asm volatile("ldmatrix.sync.aligned.m8n8.x4.shared.b16 {%0,%1,%2,%3}, [%4];"
        : "=r"(r[0]), "=r"(r[1]), "=r"(r[2]), "=r"(r[3]) : "r"(addr));
}
__device__ __forceinline__ void ldmx4t(uint32_t r[4], uint32_t addr) {
    asm volatile("ldmatrix.sync.aligned.m8n8.x4.trans.shared.b16 {%0,%1,%2,%3}, [%4];"
        : "=r"(r[0]), "=r"(r[1]), "=r"(r[2]), "=r"(r[3]) : "r"(addr));
}
__device__ __forceinline__ void mma_f16(float d[4],
                                        uint32_t a0, uint32_t a1, uint32_t a2, uint32_t a3,
                                        uint32_t b0, uint32_t b1) {
    asm volatile("mma.sync.aligned.m16n8k16.row.col.f32.f16.f16.f32 "
        "{%0,%1,%2,%3}, {%4,%5,%6,%7}, {%8,%9}, {%0,%1,%2,%3};"
        : "+f"(d[0]), "+f"(d[1]), "+f"(d[2]), "+f"(d[3])
        : "r"(a0), "r"(a1), "r"(a2), "r"(a3), "r"(b0), "r"(b1));
}

// ---------------- prep: f32 -> f16 cast ----------------
__global__ void f32_to_f16_kernel(const float* __restrict__ in, __half* __restrict__ out, size_t n4) {
    size_t i = (size_t)blockIdx.x * blockDim.x + threadIdx.x;
    if (i >= n4) return;
    float4 v = reinterpret_cast<const float4*>(in)[i];
    __half2 h0 = __floats2half2_rn(v.x, v.y);
    __half2 h1 = __floats2half2_rn(v.z, v.w);
    uint2 o;
    o.x = *reinterpret_cast<uint32_t*>(&h0);
    o.y = *reinterpret_cast<uint32_t*>(&h1);
    reinterpret_cast<uint2*>(out)[i] = o;
}

// ---------------- fp16 mma.sync GEMM: 128 thr, warp tile 64x64, BK=64 ------
// C[M,N] = A[M,K] (K-major) * B[K,N] (N-major), batched over blockIdx.z.
// CTA 128x128, BK=64 (4 k16 phases/iter), 3-stage cp.async, 2 CTAs/SM,
// 4 warps 2x2, frag double-buffering. All memory ops are asm volatile, so
// their textual order IS the SASS order: LDSM/cp.async are INTERLEAVED into
// the MMA stream (8 MMAs between each memory burst) to keep the tensor pipe
// continuously fed instead of draining at each phase head.
#define STAGES 3
#define BK 64
#define TILE_M 128
#define TILE_N 128
#define NTHREADS 128
#define AROWB 144                    // A smem: 128B data + 16 pad per row (128 rows)
#define BROWB 272                    // B smem: 256B data + 16 pad per k-row (64 rows)
#define STG_A (TILE_M * AROWB)       // 18432 B
#define STG_B (BK * BROWB)           // 17408 B
#define SM_TOTAL (STAGES * (STG_A + STG_B))   // 107520 B -> 2 CTAs/SM

#define LDM_A(dst, base, p) do {                                              \
    _Pragma("unroll")                                                         \
    for (int _mt = 0; _mt < 4; _mt++)                                         \
        ldmx4((dst)[_mt], (base) + a_lm + _mt * (16 * AROWB) + (p) * 32);     \
} while (0)
#define LDM_B(dst, base, p) do {                                              \
    _Pragma("unroll")                                                         \
    for (int _np = 0; _np < 4; _np++)                                         \
        ldmx4t((dst)[_np], (base) + b_lm + (p) * (16 * BROWB) + _np * 32);    \
} while (0)
// 8 MMAs for one mt row of the warp tile
#define MMA_MT(af, bf, mt_) do {                                              \
    _Pragma("unroll")                                                         \
    for (int _nt = 0; _nt < 8; _nt++) {                                       \
        const uint32_t* _b = (bf)[_nt >> 1];                                  \
        mma_f16(acc[mt_][_nt], (af)[mt_][0], (af)[mt_][1],                    \
                (af)[mt_][2], (af)[mt_][3],                                   \
                (_nt & 1) ? _b[2] : _b[0], (_nt & 1) ? _b[3] : _b[1]);        \
    }                                                                         \
} while (0)
#define MMA_ALL(af, bf) do {                                                  \
    MMA_MT(af, bf, 0); MMA_MT(af, bf, 1);                                     \
    MMA_MT(af, bf, 2); MMA_MT(af, bf, 3);                                     \
} while (0)

// Stage-fill halves (A: 8 cp.async, B: 8 cp.async), incremental addressing.
#define FILL_A(ao, ka) do {                                                   \
    const __half* _ap = Ag + a_o0 + (uint32_t)(ka);                           \
    uint32_t _ad = (ao) + a_d0;                                               \
    _Pragma("unroll")                                                         \
    for (int _j = 0; _j < 8; _j++) {                                          \
        cp_async16(_ad, _ap); _ad += 16 * AROWB; _ap += lda16;                \
    }                                                                         \
} while (0)
#define FILL_B(bo, ka) do {                                                   \
    const __half* _bp = Bg + b_o0 + (uint32_t)(ka) * (uint32_t)ldb;           \
    uint32_t _bd = (bo) + b_d0;                                               \
    _Pragma("unroll")                                                         \
    for (int _j = 0; _j < 8; _j++) {                                          \
        cp_async16(_bd, _bp); _bd += 8 * BROWB; _bp += ldb8;                  \
    }                                                                         \
} while (0)

template<bool RELU, bool OUT_HALF>
__global__ __launch_bounds__(NTHREADS, 2)
void gemm_f16_mma(const __half* __restrict__ A, const __half* __restrict__ B,
                  void* __restrict__ Cv,
                  int K, int lda, int ldb, int ldc,
                  long long sA, long long sB, long long sC)
{
    extern __shared__ char smem[];
    const uint32_t a_base = smem_u32(smem);
    const uint32_t b_base = a_base + STAGES * STG_A;

    const int tid = threadIdx.x;
    const int wid = tid >> 5;
    const int lane = tid & 31;
    const int lq = lane >> 2;
    const int lr = lane & 3;
    const int warpM = wid & 1;     // 0..1 (64 rows each)
    const int warpN = wid >> 1;    // 0..1 (64 cols each)

    const long long e = blockIdx.z;
    const __half* Ag = A + e * sA + (long long)blockIdx.y * TILE_M * lda;
    const __half* Bg = B + e * sB + (long long)blockIdx.x * TILE_N;   // B: [K,N]

    // cp.async base offsets (chunk 0 of this thread)
    const uint32_t a_d0 = (uint32_t)(tid >> 3) * AROWB + (uint32_t)(tid & 7) * 16;
    const uint32_t a_o0 = (uint32_t)((tid >> 3) * lda + (tid & 7) * 8);
    const uint32_t b_d0 = (uint32_t)(tid >> 4) * BROWB + (uint32_t)(tid & 15) * 16;
    const uint32_t b_o0 = (uint32_t)((tid >> 4) * ldb + (tid & 15) * 8);
    const uint32_t lda16 = 16u * (uint32_t)lda;
    const uint32_t ldb8  = 8u * (uint32_t)ldb;

    // ldmatrix source offsets (strides ≡16 mod 128 -> conflict-free)
    const uint32_t a_lm = (uint32_t)(warpM * 64 + (lane & 15)) * AROWB + ((lane >> 4) & 1) * 16;
    const uint32_t b_lm = (uint32_t)(lane & 15) * BROWB
                        + (uint32_t)(warpN * 64 + ((lane >> 4) & 1) * 8) * 2;

    const int niters = K / BK;

    // prologue: stages 0,1
    FILL_A(a_base, 0);
    FILL_B(b_base, 0);
    CP_COMMIT();
    FILL_A(a_base + STG_A, BK);
    FILL_B(b_base + STG_B, BK);
    CP_COMMIT();

    float acc[4][8][4];                           // 128 accumulators
    #pragma unroll
    for (int i = 0; i < 4; i++)
        #pragma unroll
        for (int j = 0; j < 8; j++)
            #pragma unroll
            for (int k = 0; k < 4; k++)
                acc[i][j][k] = 0.0f;

    uint32_t afX[4][4], bfX[4][4];   // even phases
    uint32_t afY[4][4], bfY[4][4];   // odd phases

    // wait stage 0, load phase-0 frags
    CP_WAIT1();
    __syncthreads();
    uint32_t As = a_base, Bs = b_base;           // current stage
    uint32_t pA = a_base + 2 * STG_A;            // prefetch slot (stage 2)
    uint32_t pB = b_base + 2 * STG_B;
    LDM_A(afX, As, 0);
    LDM_B(bfX, Bs, 0);

    int pre = STAGES - 1;

    for (int it = 0; it < niters; it++) {
        const bool doPre = (pre < niters);
        const int ka_pre = pre * BK;

        // ---- phase 0: MMA p0 interleaved with p1 frag loads + gmem prefetch ----
        MMA_MT(afX, bfX, 0);
        LDM_A(afY, As, 1);
        MMA_MT(afX, bfX, 1);
        LDM_B(bfY, Bs, 1);
        MMA_MT(afX, bfX, 2);
        if (doPre) FILL_A(pA, ka_pre);
        MMA_MT(afX, bfX, 3);
        if (doPre) {
            FILL_B(pB, ka_pre);
            pA += STG_A; if (pA == a_base + STAGES * STG_A) pA = a_base;
            pB += STG_B; if (pB == b_base + STAGES * STG_B) pB = b_base;
        }
        CP_COMMIT();
        pre++;

        // ---- phase 1: MMA p1 interleaved with p2 frag loads ----
        MMA_MT(afY, bfY, 0);
        LDM_A(afX, As, 2);
        MMA_MT(afY, bfY, 1);
        LDM_B(bfX, Bs, 2);
        MMA_MT(afY, bfY, 2);
        MMA_MT(afY, bfY, 3);

        // ---- phase 2: MMA p2 interleaved with p3 frag loads ----
        MMA_MT(afX, bfX, 0);
        LDM_A(afY, As, 3);
        MMA_MT(afX, bfX, 1);
        LDM_B(bfY, Bs, 3);
        MMA_MT(afX, bfX, 2);
        MMA_MT(afX, bfX, 3);

        // ---- phase 3: stage advance; MMA p3 interleaved with next p0 loads ----
        if (it + 1 < niters) {
            CP_WAIT1();          // stage it+1 landed (<=1 group outstanding)
            __syncthreads();     // cross-thread visibility + WAR for recycled slot
            As += STG_A; if (As == a_base + STAGES * STG_A) As = a_base;
            Bs += STG_B; if (Bs == b_base + STAGES * STG_B) Bs = b_base;
            MMA_MT(afY, bfY, 0);
            LDM_A(afX, As, 0);
            MMA_MT(afY, bfY, 1);
            LDM_B(bfX, Bs, 0);
            MMA_MT(afY, bfY, 2);
            MMA_MT(afY, bfY, 3);
        } else {
            MMA_ALL(afY, bfY);
        }
    }

    // ---- epilogue ----
    #pragma unroll
    for (int mt = 0; mt < 4; mt++) {
        const int r0 = blockIdx.y * TILE_M + warpM * 64 + mt * 16 + lq;
        #pragma unroll
        for (int nt = 0; nt < 8; nt++) {
            const int c0 = blockIdx.x * TILE_N + warpN * 64 + nt * 8 + 2 * lr;
            float v0 = acc[mt][nt][0], v1 = acc[mt][nt][1];
            float v2 = acc[mt][nt][2], v3 = acc[mt][nt][3];
            if (RELU) {
                v0 = fmaxf(v0, 0.0f); v1 = fmaxf(v1, 0.0f);
                v2 = fmaxf(v2, 0.0f); v3 = fmaxf(v3, 0.0f);
            }
            if (OUT_HALF) {
                __half* C = (__half*)Cv + e * sC;
                *reinterpret_cast<__half2*>(C + (long long)r0 * ldc + c0)       = __floats2half2_rn(v0, v1);
                *reinterpret_cast<__half2*>(C + (long long)(r0 + 8) * ldc + c0) = __floats2half2_rn(v2, v3);
            } else {
                float* C = (float*)Cv + e * sC;
                *reinterpret_cast<float2*>(C + (long long)r0 * ldc + c0)       = make_float2(v0, v1);
                *reinterpret_cast<float2*>(C + (long long)(r0 + 8) * ldc + c0) = make_float2(v2, v3);
            }
        }
    }
}

// ---------------- launch ----------------
extern "C" void kernel_launch(void* const* d_in, const int* in_sizes, int n_in,
                              void* d_out, int out_size)
{
    const float* X  = (const float*)d_in[0];
    const float* W1 = (const float*)d_in[2];
    const float* W2 = (const float*)d_in[3];
    float* Y = (float*)d_out;

    __half *Xh, *W1h, *W2h, *Hh;
    cudaGetSymbolAddress((void**)&Xh,  g_Xh);
    cudaGetSymbolAddress((void**)&W1h, g_W1h);
    cudaGetSymbolAddress((void**)&W2h, g_W2h);
    cudaGetSymbolAddress((void**)&Hh,  g_Hh);

    static bool attr_set = false;
    if (!attr_set) {
        cudaFuncSetAttribute(gemm_f16_mma<true, true>,   cudaFuncAttributeMaxDynamicSharedMemorySize, SM_TOTAL);
        cudaFuncSetAttribute(gemm_f16_mma<false, false>, cudaFuncAttributeMaxDynamicSharedMemorySize, SM_TOTAL);
        attr_set = true;
    }

    // casts
    {
        size_t n4 = (size_t)NE * NC * ND / 4;
        f32_to_f16_kernel<<<(unsigned)((n4 + 255) / 256), 256>>>(X, Xh, n4);
    }
    {
        size_t n4 = (size_t)NE * ND * NF / 4;
        f32_to_f16_kernel<<<(unsigned)((n4 + 255) / 256), 256>>>(W1, W1h, n4);
    }
    {
        size_t n4 = (size_t)NE * NF * ND / 4;
        f32_to_f16_kernel<<<(unsigned)((n4 + 255) / 256), 256>>>(W2, W2h, n4);
    }

    // GEMM1: H = relu(Xh @ W1h); M=C, N=F, K=D; ldb=NF
    {
        dim3 g(NF / TILE_N, NC / TILE_M, NE);
        gemm_f16_mma<true, true><<<g, NTHREADS, SM_TOTAL>>>(
            Xh, W1h, Hh,
            ND, ND, NF, NF,
            (long long)NC * ND, (long long)ND * NF, (long long)NC * NF);
    }
    // GEMM2: Y = H @ W2h; M=C, N=D, K=F; ldb=ND
    {
        dim3 g(ND / TILE_N, NC / TILE_M, NE);
        gemm_f16_mma<false, false><<<g, NTHREADS, SM_TOTAL>>>(
            Hh, W2h, Y,
            NF, NF, ND, ND,
            (long long)NC * NF, (long long)NF * ND, (long long)NC * ND);
    }
}

// round 16
// speedup vs baseline: 1.1029x; 1.1029x over previous
#include <cuda_runtime.h>
#include <cuda_fp16.h>
#include <cstdint>
#include <cstddef>

#define NE 8
#define NC 4096
#define ND 1024
#define NF 4096

// Device scratch (no allocs allowed)
__device__ __half g_Xh [(size_t)NE * NC * ND];   // X fp16
__device__ __half g_W1h[(size_t)NE * ND * NF];   // W1 fp16 (natural [D,F])
__device__ __half g_W2h[(size_t)NE * NF * ND];   // W2 fp16 (natural [F,D])
__device__ __half g_Hh [(size_t)NE * NC * NF];   // relu(X@W1) fp16

// ---------------- helpers ----------------
__device__ __forceinline__ uint32_t smem_u32(const void* p) {
    uint32_t a;
    asm("{ .reg .u64 t; cvta.to.shared.u64 t, %1; cvt.u32.u64 %0, t; }" : "=r"(a) : "l"(p));
    return a;
}
__device__ __forceinline__ void cp_async16(uint32_t dst, const void* src) {
    asm volatile("cp.async.cg.shared.global [%0], [%1], 16;" :: "r"(dst), "l"(src));
}

// ---- mbarrier producer/consumer (sm_80-class PTX; valid on plain sm_103) ----
#define MBAR_INIT(addr, cnt) \
    asm volatile("mbarrier.init.shared.b64 [%0], %1;" :: "r"(addr), "r"(cnt) : "memory")
#define MBAR_ARRIVE(addr) \
    asm volatile("mbarrier.arrive.shared.b64 _, [%0];" :: "r"(addr) : "memory")
// .noinc: this thread's prior cp.asyncs trigger ONE arrival counted against the
// init count (without .noinc the pending count is incremented first -> with one
// call per thread the barrier can never complete; that deadlocked R15).
#define CPA_MBAR_ARRIVE(addr) \
    asm volatile("cp.async.mbarrier.arrive.noinc.shared.b64 [%0];" :: "r"(addr) : "memory")
#define MBAR_WAIT(addr, ph) do {                                              \
    uint32_t _m = (addr); uint32_t _p = (ph); uint32_t _done;                 \
    asm volatile("{\n\t.reg .pred p;\n\t"                                     \
        "mbarrier.try_wait.parity.acquire.cta.shared::cta.b64 p, [%1], %2;\n\t" \
        "selp.b32 %0, 1, 0, p;\n\t}"                                          \
        : "=r"(_done) : "r"(_m), "r"(_p) : "memory");                         \
    if (!_done) {                                                             \
        asm volatile("{\n\t.reg .pred P1;\n\t"                                \
            "WL_%=:\n\t"                                                      \
            "mbarrier.try_wait.parity.acquire.cta.shared::cta.b64 P1, [%0], %1, 0x989680;\n\t" \
            "@P1 bra.uni WD_%=;\n\t"                                          \
            "bra.uni WL_%=;\n\t"                                              \
            "WD_%=:\n\t}"                                                     \
            :: "r"(_m), "r"(_p) : "memory");                                  \
    }                                                                         \
} while (0)

__device__ __forceinline__ void ldmx4(uint32_t r[4], uint32_t addr) {
    asm volatile("ldmatrix.sync.aligned.m8n8.x4.shared.b16 {%0,%1,%2,%3}, [%4];"
        : "=r"(r[0]), "=r"(r[1]), "=r"(r[2]), "=r"(r[3]) : "r"(addr));
}
__device__ __forceinline__ void ldmx4t(uint32_t r[4], uint32_t addr) {
    asm volatile("ldmatrix.sync.aligned.m8n8.x4.trans.shared.b16 {%0,%1,%2,%3}, [%4];"
        : "=r"(r[0]), "=r"(r[1]), "=r"(r[2]), "=r"(r[3]) : "r"(addr));
}
__device__ __forceinline__ void mma_f16(float d[4],
                                        uint32_t a0, uint32_t a1, uint32_t a2, uint32_t a3,
                                        uint32_t b0, uint32_t b1) {
    asm volatile("mma.sync.aligned.m16n8k16.row.col.f32.f16.f16.f32 "
        "{%0,%1,%2,%3}, {%4,%5,%6,%7}, {%8,%9}, {%0,%1,%2,%3};"
        : "+f"(d[0]), "+f"(d[1]), "+f"(d[2]), "+f"(d[3])
        : "r"(a0), "r"(a1), "r"(a2), "r"(a3), "r"(b0), "r"(b1));
}

// ---------------- prep: f32 -> f16 cast ----------------
__global__ void f32_to_f16_kernel(const float* __restrict__ in, __half* __restrict__ out, size_t n4) {
    size_t i = (size_t)blockIdx.x * blockDim.x + threadIdx.x;
    if (i >= n4) return;
    float4 v = reinterpret_cast<const float4*>(in)[i];
    __half2 h0 = __floats2half2_rn(v.x, v.y);
    __half2 h1 = __floats2half2_rn(v.z, v.w);
    uint2 o;
    o.x = *reinterpret_cast<uint32_t*>(&h0);
    o.y = *reinterpret_cast<uint32_t*>(&h1);
    reinterpret_cast<uint2*>(out)[i] = o;
}

// ---------------- fp16 mma.sync GEMM: 128 thr, warp tile 64x64, BK=64 ------
// C[M,N] = A[M,K] (K-major) * B[K,N] (N-major), batched over blockIdx.z.
// CTA 128x128, BK=64 (4 k16 phases/iter), 3-stage pipeline, 2 CTAs/SM,
// 4 warps 2x2, frag double-buffering (R13 block order — interleave regressed).
// Synchronization: mbarrier producer-consumer per slot (full: data-arrival via
// cp.async.mbarrier.arrive.noinc; empty: consumer arrive after last read). No
// per-iteration __syncthreads -> warp-convergence skew absorbed, not paid.
#define STAGES 3
#define BK 64
#define TILE_M 128
#define TILE_N 128
#define NTHREADS 128
#define AROWB 144                    // A smem: 128B data + 16 pad per row (128 rows)
#define BROWB 272                    // B smem: 256B data + 16 pad per k-row (64 rows)
#define STG_A (TILE_M * AROWB)       // 18432 B
#define STG_B (BK * BROWB)           // 17408 B
#define MBAR_BYTES 128               // 6 mbarriers (full[3], empty[3]) + pad
#define SM_TOTAL (MBAR_BYTES + STAGES * (STG_A + STG_B))   // 107648 B -> 2 CTAs/SM

#define LDM_A(dst, base, p) do {                                              \
    _Pragma("unroll")                                                         \
    for (int _mt = 0; _mt < 4; _mt++)                                         \
        ldmx4((dst)[_mt], (base) + a_lm + _mt * (16 * AROWB) + (p) * 32);     \
} while (0)
#define LDM_B(dst, base, p) do {                                              \
    _Pragma("unroll")                                                         \
    for (int _np = 0; _np < 4; _np++)                                         \
        ldmx4t((dst)[_np], (base) + b_lm + (p) * (16 * BROWB) + _np * 32);    \
} while (0)
#define MMA_ALL(af, bf) do {                                                  \
    _Pragma("unroll")                                                         \
    for (int _mt = 0; _mt < 4; _mt++) {                                       \
        _Pragma("unroll")                                                     \
        for (int _nt = 0; _nt < 8; _nt++) {                                   \
            const uint32_t* _b = (bf)[_nt >> 1];                              \
            mma_f16(acc[_mt][_nt], (af)[_mt][0], (af)[_mt][1],                \
                    (af)[_mt][2], (af)[_mt][3],                               \
                    (_nt & 1) ? _b[2] : _b[0], (_nt & 1) ? _b[3] : _b[1]);    \
        }                                                                     \
    }                                                                         \
} while (0)

#define FILL_A(ao, ka) do {                                                   \
    const __half* _ap = Ag + a_o0 + (uint32_t)(ka);                           \
    uint32_t _ad = (ao) + a_d0;                                               \
    _Pragma("unroll")                                                         \
    for (int _j = 0; _j < 8; _j++) {                                          \
        cp_async16(_ad, _ap); _ad += 16 * AROWB; _ap += lda16;                \
    }                                                                         \
} while (0)
#define FILL_B(bo, ka) do {                                                   \
    const __half* _bp = Bg + b_o0 + (uint32_t)(ka) * (uint32_t)ldb;           \
    uint32_t _bd = (bo) + b_d0;                                               \
    _Pragma("unroll")                                                         \
    for (int _j = 0; _j < 8; _j++) {                                          \
        cp_async16(_bd, _bp); _bd += 8 * BROWB; _bp += ldb8;                  \
    }                                                                         \
} while (0)

template<bool RELU, bool OUT_HALF>
__global__ __launch_bounds__(NTHREADS, 2)
void gemm_f16_mma(const __half* __restrict__ A, const __half* __restrict__ B,
                  void* __restrict__ Cv,
                  int K, int lda, int ldb, int ldc,
                  long long sA, long long sB, long long sC)
{
    extern __shared__ char smem[];
    const uint32_t mb_base = smem_u32(smem);
    const uint32_t a_base = mb_base + MBAR_BYTES;
    const uint32_t b_base = a_base + STAGES * STG_A;
    // full[s] = mb_base + 8*s ; empty[s] = mb_base + 24 + 8*s

    const int tid = threadIdx.x;
    const int wid = tid >> 5;
    const int lane = tid & 31;
    const int lq = lane >> 2;
    const int lr = lane & 3;
    const int warpM = wid & 1;     // 0..1 (64 rows each)
    const int warpN = wid >> 1;    // 0..1 (64 cols each)

    const long long e = blockIdx.z;
    const __half* Ag = A + e * sA + (long long)blockIdx.y * TILE_M * lda;
    const __half* Bg = B + e * sB + (long long)blockIdx.x * TILE_N;   // B: [K,N]

    // cp.async base offsets (chunk 0 of this thread)
    const uint32_t a_d0 = (uint32_t)(tid >> 3) * AROWB + (uint32_t)(tid & 7) * 16;
    const uint32_t a_o0 = (uint32_t)((tid >> 3) * lda + (tid & 7) * 8);
    const uint32_t b_d0 = (uint32_t)(tid >> 4) * BROWB + (uint32_t)(tid & 15) * 16;
    const uint32_t b_o0 = (uint32_t)((tid >> 4) * ldb + (tid & 15) * 8);
    const uint32_t lda16 = 16u * (uint32_t)lda;
    const uint32_t ldb8  = 8u * (uint32_t)ldb;

    // ldmatrix source offsets (strides ≡16 mod 128 -> conflict-free)
    const uint32_t a_lm = (uint32_t)(warpM * 64 + (lane & 15)) * AROWB + ((lane >> 4) & 1) * 16;
    const uint32_t b_lm = (uint32_t)(lane & 15) * BROWB
                        + (uint32_t)(warpN * 64 + ((lane >> 4) & 1) * 8) * 2;

    const int niters = K / BK;

    // init mbarriers (all count 128 = one arrive per thread)
    if (tid == 0) {
        #pragma unroll
        for (int s = 0; s < STAGES; s++) {
            MBAR_INIT(mb_base + 8 * s, NTHREADS);       // full[s]
            MBAR_INIT(mb_base + 24 + 8 * s, NTHREADS);  // empty[s]
        }
    }
    __syncthreads();

    // prologue: fill slots 0,1 (never consumed yet -> no empty wait)
    FILL_A(a_base, 0);
    FILL_B(b_base, 0);
    CPA_MBAR_ARRIVE(mb_base + 0);
    FILL_A(a_base + STG_A, BK);
    FILL_B(b_base + STG_B, BK);
    CPA_MBAR_ARRIVE(mb_base + 8);

    float acc[4][8][4];
    #pragma unroll
    for (int i = 0; i < 4; i++)
        #pragma unroll
        for (int j = 0; j < 8; j++)
            #pragma unroll
            for (int k = 0; k < 4; k++)
                acc[i][j][k] = 0.0f;

    uint32_t afX[4][4], bfX[4][4];   // even phases
    uint32_t afY[4][4], bfY[4][4];   // odd phases

    // wait slot 0 data (fill #0 completes phase 0 -> parity 0), load p0 frags
    MBAR_WAIT(mb_base + 0, 0);
    uint32_t As = a_base, Bs = b_base;
    uint32_t pA = a_base + 2 * STG_A;            // prefetch slot (stage 2)
    uint32_t pB = b_base + 2 * STG_B;
    LDM_A(afX, As, 0);
    LDM_B(bfX, Bs, 0);

    int pre = STAGES - 1;

    for (int it = 0; it < niters; it++) {
        // ---- phase 0: load p1 frags, gated refill of slot (it-1)%3, MMA p0 ----
        LDM_A(afY, As, 1);
        LDM_B(bfY, Bs, 1);
        if (pre < niters) {
            const int ps = pre - (pre / STAGES) * STAGES;        // pre % 3
            if (pre >= STAGES) {
                // refill #m of slot ps (m = pre/3): wait consumers' phase m-1
                MBAR_WAIT(mb_base + 24 + 8 * ps, (uint32_t)((pre / STAGES + 1) & 1));
            }
            FILL_A(pA, pre * BK);
            FILL_B(pB, pre * BK);
            CPA_MBAR_ARRIVE(mb_base + 8 * ps);                   // full[ps] on data arrival
            pA += STG_A; if (pA == a_base + STAGES * STG_A) pA = a_base;
            pB += STG_B; if (pB == b_base + STAGES * STG_B) pB = b_base;
        }
        pre++;
        MMA_ALL(afX, bfX);

        // ---- phase 1: load p2, MMA p1 ----
        LDM_A(afX, As, 2);
        LDM_B(bfX, Bs, 2);
        MMA_ALL(afY, bfY);

        // ---- phase 2: load p3 (last read of slot it%3), release it, MMA p2 ----
        LDM_A(afY, As, 3);
        LDM_B(bfY, Bs, 3);
        {
            const int cs = it - (it / STAGES) * STAGES;          // it % 3
            MBAR_ARRIVE(mb_base + 24 + 8 * cs);                  // empty[cs]
        }
        MMA_ALL(afX, bfX);

        // ---- phase 3: wait next slot's data, load next p0, MMA p3 ----
        if (it + 1 < niters) {
            const int nit = it + 1;
            const int ns = nit - (nit / STAGES) * STAGES;        // (it+1) % 3
            MBAR_WAIT(mb_base + 8 * ns, (uint32_t)((nit / STAGES) & 1));
            As += STG_A; if (As == a_base + STAGES * STG_A) As = a_base;
            Bs += STG_B; if (Bs == b_base + STAGES * STG_B) Bs = b_base;
            LDM_A(afX, As, 0);
            LDM_B(bfX, Bs, 0);
        }
        MMA_ALL(afY, bfY);
    }

    // ---- epilogue ----
    #pragma unroll
    for (int mt = 0; mt < 4; mt++) {
        const int r0 = blockIdx.y * TILE_M + warpM * 64 + mt * 16 + lq;
        #pragma unroll
        for (int nt = 0; nt < 8; nt++) {
            const int c0 = blockIdx.x * TILE_N + warpN * 64 + nt * 8 + 2 * lr;
            float v0 = acc[mt][nt][0], v1 = acc[mt][nt][1];
            float v2 = acc[mt][nt][2], v3 = acc[mt][nt][3];
            if (RELU) {
                v0 = fmaxf(v0, 0.0f); v1 = fmaxf(v1, 0.0f);
                v2 = fmaxf(v2, 0.0f); v3 = fmaxf(v3, 0.0f);
            }
            if (OUT_HALF) {
                __half* C = (__half*)Cv + e * sC;
                *reinterpret_cast<__half2*>(C + (long long)r0 * ldc + c0)       = __floats2half2_rn(v0, v1);
                *reinterpret_cast<__half2*>(C + (long long)(r0 + 8) * ldc + c0) = __floats2half2_rn(v2, v3);
            } else {
                float* C = (float*)Cv + e * sC;
                *reinterpret_cast<float2*>(C + (long long)r0 * ldc + c0)       = make_float2(v0, v1);
                *reinterpret_cast<float2*>(C + (long long)(r0 + 8) * ldc + c0) = make_float2(v2, v3);
            }
        }
    }
}

// ---------------- launch ----------------
extern "C" void kernel_launch(void* const* d_in, const int* in_sizes, int n_in,
                              void* d_out, int out_size)
{
    const float* X  = (const float*)d_in[0];
    const float* W1 = (const float*)d_in[2];
    const float* W2 = (const float*)d_in[3];
    float* Y = (float*)d_out;

    __half *Xh, *W1h, *W2h, *Hh;
    cudaGetSymbolAddress((void**)&Xh,  g_Xh);
    cudaGetSymbolAddress((void**)&W1h, g_W1h);
    cudaGetSymbolAddress((void**)&W2h, g_W2h);
    cudaGetSymbolAddress((void**)&Hh,  g_Hh);

    static bool attr_set = false;
    if (!attr_set) {
        cudaFuncSetAttribute(gemm_f16_mma<true, true>,   cudaFuncAttributeMaxDynamicSharedMemorySize, SM_TOTAL);
        cudaFuncSetAttribute(gemm_f16_mma<false, false>, cudaFuncAttributeMaxDynamicSharedMemorySize, SM_TOTAL);
        attr_set = true;
    }

    // casts
    {
        size_t n4 = (size_t)NE * NC * ND / 4;
        f32_to_f16_kernel<<<(unsigned)((n4 + 255) / 256), 256>>>(X, Xh, n4);
    }
    {
        size_t n4 = (size_t)NE * ND * NF / 4;
        f32_to_f16_kernel<<<(unsigned)((n4 + 255) / 256), 256>>>(W1, W1h, n4);
    }
    {
        size_t n4 = (size_t)NE * NF * ND / 4;
        f32_to_f16_kernel<<<(unsigned)((n4 + 255) / 256), 256>>>(W2, W2h, n4);
    }

    // GEMM1: H = relu(Xh @ W1h); M=C, N=F, K=D; ldb=NF
    {
        dim3 g(NF / TILE_N, NC / TILE_M, NE);
        gemm_f16_mma<true, true><<<g, NTHREADS, SM_TOTAL>>>(
            Xh, W1h, Hh,
            ND, ND, NF, NF,
            (long long)NC * ND, (long long)ND * NF, (long long)NC * NF);
    }
    // GEMM2: Y = H @ W2h; M=C, N=D, K=F; ldb=ND
    {
        dim3 g(ND / TILE_N, NC / TILE_M, NE);
        gemm_f16_mma<false, false><<<g, NTHREADS, SM_TOTAL>>>(
            Hh, W2h, Y,
            NF, NF, ND, ND,
            (long long)NC * NF, (long long)NF * ND, (long long)NC * ND);
    }
}

// round 17
// speedup vs baseline: 1.1130x; 1.0091x over previous
#include <cuda_runtime.h>
#include <cuda_fp16.h>
#include <cstdint>
#include <cstddef>

#define NE 8
#define NC 4096
#define ND 1024
#define NF 4096

// Device scratch (no allocs allowed)
__device__ __half g_Xh [(size_t)NE * NC * ND];   // X fp16
__device__ __half g_W1h[(size_t)NE * ND * NF];   // W1 fp16 (natural [D,F])
__device__ __half g_W2h[(size_t)NE * NF * ND];   // W2 fp16 (natural [F,D])
__device__ __half g_Hh [(size_t)NE * NC * NF];   // relu(X@W1) fp16

// ---------------- helpers ----------------
__device__ __forceinline__ uint32_t smem_u32(const void* p) {
    uint32_t a;
    asm("{ .reg .u64 t; cvta.to.shared.u64 t, %1; cvt.u32.u64 %0, t; }" : "=r"(a) : "l"(p));
    return a;
}
__device__ __forceinline__ void cp_async16(uint32_t dst, const void* src) {
    asm volatile("cp.async.cg.shared.global [%0], [%1], 16;" :: "r"(dst), "l"(src));
}

// ---- mbarrier producer/consumer ----
#define MBAR_INIT(addr, cnt) \
    asm volatile("mbarrier.init.shared.b64 [%0], %1;" :: "r"(addr), "r"(cnt) : "memory")
#define MBAR_ARRIVE(addr) \
    asm volatile("mbarrier.arrive.shared.b64 _, [%0];" :: "r"(addr) : "memory")
// .noinc: one arrival per thread counted against init count (R15 deadlocked without it)
#define CPA_MBAR_ARRIVE(addr) \
    asm volatile("cp.async.mbarrier.arrive.noinc.shared.b64 [%0];" :: "r"(addr) : "memory")
#define MBAR_WAIT(addr, ph) do {                                              \
    uint32_t _m = (addr); uint32_t _p = (ph); uint32_t _done;                 \
    asm volatile("{\n\t.reg .pred p;\n\t"                                     \
        "mbarrier.try_wait.parity.acquire.cta.shared::cta.b64 p, [%1], %2;\n\t" \
        "selp.b32 %0, 1, 0, p;\n\t}"                                          \
        : "=r"(_done) : "r"(_m), "r"(_p) : "memory");                         \
    if (!_done) {                                                             \
        asm volatile("{\n\t.reg .pred P1;\n\t"                                \
            "WL_%=:\n\t"                                                      \
            "mbarrier.try_wait.parity.acquire.cta.shared::cta.b64 P1, [%0], %1, 0x989680;\n\t" \
            "@P1 bra.uni WD_%=;\n\t"                                          \
            "bra.uni WL_%=;\n\t"                                              \
            "WD_%=:\n\t}"                                                     \
            :: "r"(_m), "r"(_p) : "memory");                                  \
    }                                                                         \
} while (0)

__device__ __forceinline__ void ldmx4(uint32_t r[4], uint32_t addr) {
    asm volatile("ldmatrix.sync.aligned.m8n8.x4.shared.b16 {%0,%1,%2,%3}, [%4];"
        : "=r"(r[0]), "=r"(r[1]), "=r"(r[2]), "=r"(r[3]) : "r"(addr));
}
__device__ __forceinline__ void ldmx4t(uint32_t r[4], uint32_t addr) {
    asm volatile("ldmatrix.sync.aligned.m8n8.x4.trans.shared.b16 {%0,%1,%2,%3}, [%4];"
        : "=r"(r[0]), "=r"(r[1]), "=r"(r[2]), "=r"(r[3]) : "r"(addr));
}
__device__ __forceinline__ void mma_f16(float d[4],
                                        uint32_t a0, uint32_t a1, uint32_t a2, uint32_t a3,
                                        uint32_t b0, uint32_t b1) {
    asm volatile("mma.sync.aligned.m16n8k16.row.col.f32.f16.f16.f32 "
        "{%0,%1,%2,%3}, {%4,%5,%6,%7}, {%8,%9}, {%0,%1,%2,%3};"
        : "+f"(d[0]), "+f"(d[1]), "+f"(d[2]), "+f"(d[3])
        : "r"(a0), "r"(a1), "r"(a2), "r"(a3), "r"(b0), "r"(b1));
}

// ---------------- prep: one merged f32 -> f16 cast over 3 buffers ----------
__global__ void cast_all_kernel(const float* __restrict__ x,  __half* __restrict__ xo,  size_t nx4,
                                const float* __restrict__ w1, __half* __restrict__ w1o, size_t nw14,
                                const float* __restrict__ w2, __half* __restrict__ w2o, size_t nw24)
{
    size_t i = (size_t)blockIdx.x * blockDim.x + threadIdx.x;
    const float* in; __half* out; size_t idx;
    if (i < nx4)                 { in = x;  out = xo;  idx = i; }
    else if (i < nx4 + nw14)     { in = w1; out = w1o; idx = i - nx4; }
    else if (i < nx4 + nw14 + nw24) { in = w2; out = w2o; idx = i - nx4 - nw14; }
    else return;
    float4 v = reinterpret_cast<const float4*>(in)[idx];
    __half2 h0 = __floats2half2_rn(v.x, v.y);
    __half2 h1 = __floats2half2_rn(v.z, v.w);
    uint2 o;
    o.x = *reinterpret_cast<uint32_t*>(&h0);
    o.y = *reinterpret_cast<uint32_t*>(&h1);
    reinterpret_cast<uint2*>(out)[idx] = o;
}

// ---------------- fp16 mma.sync GEMM: 128 thr, warp tile 64x64, BK=64 ------
// R16 structure (mbarrier producer-consumer). Changes:
//  - incremental slot counters (no div/mod by 3 in the mainloop)
//  - phase-0 fills + empty-wait moved AFTER the phase-0 MMA burst
#define STAGES 3
#define BK 64
#define TILE_M 128
#define TILE_N 128
#define NTHREADS 128
#define AROWB 144
#define BROWB 272
#define STG_A (TILE_M * AROWB)       // 18432 B
#define STG_B (BK * BROWB)           // 17408 B
#define MBAR_BYTES 128
#define SM_TOTAL (MBAR_BYTES + STAGES * (STG_A + STG_B))   // 107648 B -> 2 CTAs/SM

#define LDM_A(dst, base, p) do {                                              \
    _Pragma("unroll")                                                         \
    for (int _mt = 0; _mt < 4; _mt++)                                         \
        ldmx4((dst)[_mt], (base) + a_lm + _mt * (16 * AROWB) + (p) * 32);     \
} while (0)
#define LDM_B(dst, base, p) do {                                              \
    _Pragma("unroll")                                                         \
    for (int _np = 0; _np < 4; _np++)                                         \
        ldmx4t((dst)[_np], (base) + b_lm + (p) * (16 * BROWB) + _np * 32);    \
} while (0)
#define MMA_ALL(af, bf) do {                                                  \
    _Pragma("unroll")                                                         \
    for (int _mt = 0; _mt < 4; _mt++) {                                       \
        _Pragma("unroll")                                                     \
        for (int _nt = 0; _nt < 8; _nt++) {                                   \
            const uint32_t* _b = (bf)[_nt >> 1];                              \
            mma_f16(acc[_mt][_nt], (af)[_mt][0], (af)[_mt][1],                \
                    (af)[_mt][2], (af)[_mt][3],                               \
                    (_nt & 1) ? _b[2] : _b[0], (_nt & 1) ? _b[3] : _b[1]);    \
        }                                                                     \
    }                                                                         \
} while (0)

#define FILL_A(ao, ka) do {                                                   \
    const __half* _ap = Ag + a_o0 + (uint32_t)(ka);                           \
    uint32_t _ad = (ao) + a_d0;                                               \
    _Pragma("unroll")                                                         \
    for (int _j = 0; _j < 8; _j++) {                                          \
        cp_async16(_ad, _ap); _ad += 16 * AROWB; _ap += lda16;                \
    }                                                                         \
} while (0)
#define FILL_B(bo, ka) do {                                                   \
    const __half* _bp = Bg + b_o0 + (uint32_t)(ka) * (uint32_t)ldb;           \
    uint32_t _bd = (bo) + b_d0;                                               \
    _Pragma("unroll")                                                         \
    for (int _j = 0; _j < 8; _j++) {                                          \
        cp_async16(_bd, _bp); _bd += 8 * BROWB; _bp += ldb8;                  \
    }                                                                         \
} while (0)

template<bool RELU, bool OUT_HALF>
__global__ __launch_bounds__(NTHREADS, 2)
void gemm_f16_mma(const __half* __restrict__ A, const __half* __restrict__ B,
                  void* __restrict__ Cv,
                  int K, int lda, int ldb, int ldc,
                  long long sA, long long sB, long long sC)
{
    extern __shared__ char smem[];
    const uint32_t mb_base = smem_u32(smem);
    const uint32_t a_base = mb_base + MBAR_BYTES;
    const uint32_t b_base = a_base + STAGES * STG_A;
    // full[s] = mb_base + 8*s ; empty[s] = mb_base + 24 + 8*s

    const int tid = threadIdx.x;
    const int wid = tid >> 5;
    const int lane = tid & 31;
    const int lq = lane >> 2;
    const int lr = lane & 3;
    const int warpM = wid & 1;
    const int warpN = wid >> 1;

    const long long e = blockIdx.z;
    const __half* Ag = A + e * sA + (long long)blockIdx.y * TILE_M * lda;
    const __half* Bg = B + e * sB + (long long)blockIdx.x * TILE_N;   // B: [K,N]

    const uint32_t a_d0 = (uint32_t)(tid >> 3) * AROWB + (uint32_t)(tid & 7) * 16;
    const uint32_t a_o0 = (uint32_t)((tid >> 3) * lda + (tid & 7) * 8);
    const uint32_t b_d0 = (uint32_t)(tid >> 4) * BROWB + (uint32_t)(tid & 15) * 16;
    const uint32_t b_o0 = (uint32_t)((tid >> 4) * ldb + (tid & 15) * 8);
    const uint32_t lda16 = 16u * (uint32_t)lda;
    const uint32_t ldb8  = 8u * (uint32_t)ldb;

    const uint32_t a_lm = (uint32_t)(warpM * 64 + (lane & 15)) * AROWB + ((lane >> 4) & 1) * 16;
    const uint32_t b_lm = (uint32_t)(lane & 15) * BROWB
                        + (uint32_t)(warpN * 64 + ((lane >> 4) & 1) * 8) * 2;

    const int niters = K / BK;

    if (tid == 0) {
        #pragma unroll
        for (int s = 0; s < STAGES; s++) {
            MBAR_INIT(mb_base + 8 * s, NTHREADS);       // full[s]
            MBAR_INIT(mb_base + 24 + 8 * s, NTHREADS);  // empty[s]
        }
    }
    __syncthreads();

    // prologue: fill slots 0,1 (never consumed -> no empty wait)
    FILL_A(a_base, 0);
    FILL_B(b_base, 0);
    CPA_MBAR_ARRIVE(mb_base + 0);
    FILL_A(a_base + STG_A, BK);
    FILL_B(b_base + STG_B, BK);
    CPA_MBAR_ARRIVE(mb_base + 8);

    float acc[4][8][4];
    #pragma unroll
    for (int i = 0; i < 4; i++)
        #pragma unroll
        for (int j = 0; j < 8; j++)
            #pragma unroll
            for (int k = 0; k < 4; k++)
                acc[i][j][k] = 0.0f;

    uint32_t afX[4][4], bfX[4][4];
    uint32_t afY[4][4], bfY[4][4];

    MBAR_WAIT(mb_base + 0, 0);
    uint32_t As = a_base, Bs = b_base;
    uint32_t pA = a_base + 2 * STG_A;
    uint32_t pB = b_base + 2 * STG_B;
    LDM_A(afX, As, 0);
    LDM_B(bfX, Bs, 0);

    // incremental pipeline state (no div/mod in loop)
    int pre = STAGES - 1;            // next k-stage index to fill
    int ps = STAGES - 1;             // pre % 3
    int fill_round = 1;              // pre / 3 (starts at 1 when ps wraps? no: pre=2 -> round 0)
    // careful: pre=2 => ps=2, round 0. Maintain: when ps wraps past 2 -> round++
    fill_round = 0;
    int cs = 0;                      // it % 3 (consumer slot)
    int ns = 1;                      // (it+1) % 3
    int nround_par = 0;              // ((it+1)/3) & 1
    int ka_pre = (STAGES - 1) * BK;

    for (int it = 0; it < niters; it++) {
        // ---- phase 0: load p1 frags, MMA p0 FIRST, then gated refill ----
        LDM_A(afY, As, 1);
        LDM_B(bfY, Bs, 1);
        MMA_ALL(afX, bfX);

        if (pre < niters) {
            if (pre >= STAGES) {
                // refill #round of slot ps: wait consumers' phase (round-1)&1
                MBAR_WAIT(mb_base + 24 + 8 * ps, (uint32_t)((fill_round + 1) & 1));
            }
            FILL_A(pA, ka_pre);
            FILL_B(pB, ka_pre);
            CPA_MBAR_ARRIVE(mb_base + 8 * ps);
            pA += STG_A; if (pA == a_base + STAGES * STG_A) pA = a_base;
            pB += STG_B; if (pB == b_base + STAGES * STG_B) pB = b_base;
        }
        pre++; ka_pre += BK;
        ps++; if (ps == STAGES) { ps = 0; fill_round++; }

        // ---- phase 1: load p2, MMA p1 ----
        LDM_A(afX, As, 2);
        LDM_B(bfX, Bs, 2);
        MMA_ALL(afY, bfY);

        // ---- phase 2: load p3 (last read of slot cs), release it, MMA p2 ----
        LDM_A(afY, As, 3);
        LDM_B(bfY, Bs, 3);
        MBAR_ARRIVE(mb_base + 24 + 8 * cs);              // empty[cs]
        MMA_ALL(afX, bfX);

        // ---- phase 3: wait next slot's data, load next p0, MMA p3 ----
        if (it + 1 < niters) {
            MBAR_WAIT(mb_base + 8 * ns, (uint32_t)nround_par);
            As += STG_A; if (As == a_base + STAGES * STG_A) As = a_base;
            Bs += STG_B; if (Bs == b_base + STAGES * STG_B) Bs = b_base;
            LDM_A(afX, As, 0);
            LDM_B(bfX, Bs, 0);
        }
        MMA_ALL(afY, bfY);

        // advance consumer slot counters
        cs++; if (cs == STAGES) cs = 0;
        ns++; if (ns == STAGES) { ns = 0; nround_par ^= 1; }
    }

    // ---- epilogue ----
    #pragma unroll
    for (int mt = 0; mt < 4; mt++) {
        const int r0 = blockIdx.y * TILE_M + warpM * 64 + mt * 16 + lq;
        #pragma unroll
        for (int nt = 0; nt < 8; nt++) {
            const int c0 = blockIdx.x * TILE_N + warpN * 64 + nt * 8 + 2 * lr;
            float v0 = acc[mt][nt][0], v1 = acc[mt][nt][1];
            float v2 = acc[mt][nt][2], v3 = acc[mt][nt][3];
            if (RELU) {
                v0 = fmaxf(v0, 0.0f); v1 = fmaxf(v1, 0.0f);
                v2 = fmaxf(v2, 0.0f); v3 = fmaxf(v3, 0.0f);
            }
            if (OUT_HALF) {
                __half* C = (__half*)Cv + e * sC;
                *reinterpret_cast<__half2*>(C + (long long)r0 * ldc + c0)       = __floats2half2_rn(v0, v1);
                *reinterpret_cast<__half2*>(C + (long long)(r0 + 8) * ldc + c0) = __floats2half2_rn(v2, v3);
            } else {
                float* C = (float*)Cv + e * sC;
                *reinterpret_cast<float2*>(C + (long long)r0 * ldc + c0)       = make_float2(v0, v1);
                *reinterpret_cast<float2*>(C + (long long)(r0 + 8) * ldc + c0) = make_float2(v2, v3);
            }
        }
    }
}

// ---------------- launch ----------------
extern "C" void kernel_launch(void* const* d_in, const int* in_sizes, int n_in,
                              void* d_out, int out_size)
{
    const float* X  = (const float*)d_in[0];
    const float* W1 = (const float*)d_in[2];
    const float* W2 = (const float*)d_in[3];
    float* Y = (float*)d_out;

    __half *Xh, *W1h, *W2h, *Hh;
    cudaGetSymbolAddress((void**)&Xh,  g_Xh);
    cudaGetSymbolAddress((void**)&W1h, g_W1h);
    cudaGetSymbolAddress((void**)&W2h, g_W2h);
    cudaGetSymbolAddress((void**)&Hh,  g_Hh);

    static bool attr_set = false;
    if (!attr_set) {
        cudaFuncSetAttribute(gemm_f16_mma<true, true>,   cudaFuncAttributeMaxDynamicSharedMemorySize, SM_TOTAL);
        cudaFuncSetAttribute(gemm_f16_mma<false, false>, cudaFuncAttributeMaxDynamicSharedMemorySize, SM_TOTAL);
        attr_set = true;
    }

    // merged cast (X, W1, W2 -> fp16) in one launch
    {
        size_t nx4  = (size_t)NE * NC * ND / 4;
        size_t nw14 = (size_t)NE * ND * NF / 4;
        size_t nw24 = (size_t)NE * NF * ND / 4;
        size_t tot = nx4 + nw14 + nw24;
        cast_all_kernel<<<(unsigned)((tot + 255) / 256), 256>>>(
            X, Xh, nx4, W1, W1h, nw14, W2, W2h, nw24);
    }

    // GEMM1: H = relu(Xh @ W1h); M=C, N=F, K=D; ldb=NF
    {
        dim3 g(NF / TILE_N, NC / TILE_M, NE);
        gemm_f16_mma<true, true><<<g, NTHREADS, SM_TOTAL>>>(
            Xh, W1h, Hh,
            ND, ND, NF, NF,
            (long long)NC * ND, (long long)ND * NF, (long long)NC * NF);
    }
    // GEMM2: Y = H @ W2h; M=C, N=D, K=F; ldb=ND
    {
        dim3 g(ND / TILE_N, NC / TILE_M, NE);
        gemm_f16_mma<false, false><<<g, NTHREADS, SM_TOTAL>>>(
            Hh, W2h, Y,
            NF, NF, ND, ND,
            (long long)NC * NF, (long long)NF * ND, (long long)NC * ND);
    }
}